// round 3
// baseline (speedup 1.0000x reference)
#include <cuda_runtime.h>
#include <cstdint>

// ---------------- problem constants ----------------
#define NN 50000
#define EE 800000
#define GG 256
#define HH 64
#define INW 128

// ---------------- device scratch (no allocation allowed) ----------------
__device__ float g_zl[NN * HH];
__device__ float g_zr[NN * HH];
__device__ float g_agg[NN * HH];
__device__ float g_h[NN * HH];
__device__ float g_cnt[NN];
__device__ float g_inv[NN];
__device__ float g_pool[GG * HH];
__device__ float g_pcnt[GG];
__device__ float g_cA[GG * 256];
__device__ float g_cB[GG * 256];

// ---------------- helpers ----------------
__device__ __forceinline__ void red_add_v4(float* a, float4 v) {
    asm volatile("red.global.add.v4.f32 [%0], {%1,%2,%3,%4};"
                 :: "l"(a), "f"(v.x), "f"(v.y), "f"(v.z), "f"(v.w) : "memory");
}
__device__ __forceinline__ void red_add_f(float* a, float v) {
    asm volatile("red.global.add.f32 [%0], %1;" :: "l"(a), "f"(v) : "memory");
}

// ---------------- edge-degree count ----------------
__global__ void k_count(const int* __restrict__ dst, float* __restrict__ cnt, int E) {
    int e = blockIdx.x * blockDim.x + threadIdx.x;
    if (e >= E) return;
    unsigned d = (unsigned)dst[e];
    if (d < NN) red_add_f(cnt + d, 1.0f);
}

__global__ void k_inv(const float* __restrict__ cnt, float* __restrict__ inv, int N) {
    int i = blockIdx.x * blockDim.x + threadIdx.x;
    if (i >= N) return;
    inv[i] = 1.0f / fmaxf(cnt[i], 1.0f);
}

// ---------------- dual GEMM: z = x @ [Wl | Wr]  (DIN x 64 each) ----------------
// block = 256 threads, tile = 32 nodes x 128 cols, thread tile = 4 nodes x 4 cols
template <int DIN>
__global__ void k_gemm_dual(const float* __restrict__ x,
                            const float* __restrict__ Wl,
                            const float* __restrict__ Wr,
                            float* __restrict__ zl,
                            float* __restrict__ zr, int N) {
    extern __shared__ float sm[];
    float* ws = sm;                 // DIN * 128
    float* xs = sm + DIN * 128;     // 32 * DIN
    const int tid = threadIdx.x;

    for (int i = tid; i < DIN * 128; i += 256) {
        int k = i >> 7, j = i & 127;
        ws[i] = (j < 64) ? Wl[k * 64 + j] : Wr[k * 64 + (j - 64)];
    }
    const int base = blockIdx.x * 32;
    for (int i = tid; i < 32 * DIN; i += 256) {
        int n = i / DIN, k = i % DIN;
        int node = base + n;
        xs[i] = (node < N) ? x[(long long)node * DIN + k] : 0.0f;
    }
    __syncthreads();

    const int tx = tid & 31;   // column group -> cols [4*tx, 4*tx+3]
    const int ty = tid >> 5;   // node group  -> nodes [base+4*ty, base+4*ty+3]
    float acc[4][4];
#pragma unroll
    for (int a = 0; a < 4; a++)
#pragma unroll
        for (int b = 0; b < 4; b++) acc[a][b] = 0.0f;

    const float* xs0 = xs + (ty * 4) * DIN;
#pragma unroll 4
    for (int k = 0; k < DIN; k++) {
        float4 w = *(const float4*)(ws + k * 128 + tx * 4);
        float xv[4];
#pragma unroll
        for (int a = 0; a < 4; a++) xv[a] = xs0[a * DIN + k];
#pragma unroll
        for (int a = 0; a < 4; a++) {
            acc[a][0] += xv[a] * w.x;
            acc[a][1] += xv[a] * w.y;
            acc[a][2] += xv[a] * w.z;
            acc[a][3] += xv[a] * w.w;
        }
    }

    const int col = tx * 4;
#pragma unroll
    for (int a = 0; a < 4; a++) {
        int node = base + ty * 4 + a;
        if (node < N) {
            float4 v = make_float4(acc[a][0], acc[a][1], acc[a][2], acc[a][3]);
            if (col < 64)
                *(float4*)(zl + (long long)node * 64 + col) = v;
            else
                *(float4*)(zr + (long long)node * 64 + (col - 64)) = v;
        }
    }
}

// ---------------- edge scatter: agg[dst] += zl[src] (64 floats via 16 lanes) ----------------
__global__ void k_scatter(const int* __restrict__ src, const int* __restrict__ dst,
                          const float* __restrict__ zl, float* __restrict__ agg, int E) {
    long long idx = (long long)blockIdx.x * blockDim.x + threadIdx.x;
    int e = (int)(idx >> 4);
    int c = ((int)idx & 15) * 4;
    if (e >= E) return;
    unsigned s = (unsigned)src[e];
    unsigned d = (unsigned)dst[e];
    if (s >= NN || d >= NN) return;
    float4 v = *(const float4*)(zl + (long long)s * 64 + c);
    red_add_v4(agg + (long long)d * 64 + c, v);
}

// ---------------- combine: h = agg*inv + zr + bl ----------------
__global__ void k_combine(const float* __restrict__ agg, const float* __restrict__ inv,
                          const float* __restrict__ zr, const float* __restrict__ bl,
                          float* __restrict__ h, int N) {
    long long idx = (long long)blockIdx.x * blockDim.x + threadIdx.x;
    int node = (int)(idx >> 4);
    int c = ((int)idx & 15) * 4;
    if (node >= N) return;
    float iv = inv[node];
    float4 a = *(const float4*)(agg + (long long)node * 64 + c);
    float4 r = *(const float4*)(zr + (long long)node * 64 + c);
    float4 b = *(const float4*)(bl + c);
    float4 o;
    o.x = a.x * iv + r.x + b.x;
    o.y = a.y * iv + r.y + b.y;
    o.z = a.z * iv + r.z + b.z;
    o.w = a.w * iv + r.w + b.w;
    *(float4*)(h + (long long)node * 64 + c) = o;
}

// ---------------- global mean pool (sum + counts) ----------------
__global__ void k_pool(const float* __restrict__ h, const int* __restrict__ batch,
                       float* __restrict__ pool, float* __restrict__ pcnt, int N) {
    long long idx = (long long)blockIdx.x * blockDim.x + threadIdx.x;
    int node = (int)(idx >> 4);
    int c = ((int)idx & 15) * 4;
    if (node >= N) return;
    unsigned b = (unsigned)batch[node];
    if (b >= GG) return;
    float4 v = *(const float4*)(h + (long long)node * 64 + c);
    red_add_v4(pool + (long long)b * 64 + c, v);
    if (c == 0) red_add_f(pcnt + b, 1.0f);
}

__global__ void k_poolfin(const float* __restrict__ pool, const float* __restrict__ pcnt,
                          float* __restrict__ c0) {
    int idx = blockIdx.x * blockDim.x + threadIdx.x;
    if (idx >= GG * 64) return;
    int g = idx >> 6;
    c0[idx] = pool[idx] / fmaxf(pcnt[g], 1.0f);
}

// ---------------- fused Linear + BatchNorm(batch stats) + tanh ----------------
// grid.x = dout, block = 256 (one thread per graph-row)
__global__ void k_lin_bn_tanh(const float* __restrict__ in, int din,
                              const float* __restrict__ W, const float* __restrict__ b,
                              const float* __restrict__ gamma, const float* __restrict__ beta,
                              float* __restrict__ out, int dout) {
    __shared__ float ws[256];
    __shared__ float red[256];
    const int col = blockIdx.x;
    const int tid = threadIdx.x;
    if (tid < din) ws[tid] = W[tid * dout + col];
    __syncthreads();

    float val = b[col];
    const float* row = in + tid * din;
    for (int k = 0; k < din; k++) val += row[k] * ws[k];

    // mean over 256 rows
    red[tid] = val;
    __syncthreads();
    for (int s = 128; s > 0; s >>= 1) {
        if (tid < s) red[tid] += red[tid + s];
        __syncthreads();
    }
    float mean = red[0] * (1.0f / 256.0f);
    __syncthreads();

    float dv = val - mean;
    red[tid] = dv * dv;
    __syncthreads();
    for (int s = 128; s > 0; s >>= 1) {
        if (tid < s) red[tid] += red[tid + s];
        __syncthreads();
    }
    float var = red[0] * (1.0f / 256.0f);

    float y = dv * rsqrtf(var + 1e-5f) * gamma[col] + beta[col];
    out[tid * dout + col] = tanhf(y);
}

// ---------------- final linear 64 -> 10 ----------------
__global__ void k_final(const float* __restrict__ in, const float* __restrict__ W,
                        const float* __restrict__ b, float* __restrict__ out) {
    __shared__ float ws[64 * 10];
    __shared__ float bs[10];
    const int tid = threadIdx.x;
    for (int i = tid; i < 640; i += 256) ws[i] = W[i];
    if (tid < 10) bs[tid] = b[tid];
    __syncthreads();
    float acc[10];
#pragma unroll
    for (int j = 0; j < 10; j++) acc[j] = bs[j];
    const float* row = in + tid * 64;
    for (int k = 0; k < 64; k++) {
        float xv = row[k];
#pragma unroll
        for (int j = 0; j < 10; j++) acc[j] += xv * ws[k * 10 + j];
    }
#pragma unroll
    for (int j = 0; j < 10; j++) out[tid * 10 + j] = acc[j];
}

// ---------------- launch ----------------
extern "C" void kernel_launch(void* const* d_in, const int* in_sizes, int n_in,
                              void* d_out, int out_size) {
    const float* x = (const float*)d_in[0];
    const int* ei = (const int*)d_in[1];     // int32 (JAX x64 disabled truncates int64)
    const int* batch = (const int*)d_in[2];
    const float* W1l = (const float*)d_in[3];
    const float* b1l = (const float*)d_in[4];
    const float* W1r = (const float*)d_in[5];
    const float* W2l = (const float*)d_in[6];
    const float* b2l = (const float*)d_in[7];
    const float* W2r = (const float*)d_in[8];
    const float* W3l = (const float*)d_in[9];
    const float* b3l = (const float*)d_in[10];
    const float* W3r = (const float*)d_in[11];
    const float* lin1_w = (const float*)d_in[12];
    const float* lin1_b = (const float*)d_in[13];
    const float* g1 = (const float*)d_in[14];
    const float* be1 = (const float*)d_in[15];
    const float* lin2_w = (const float*)d_in[16];
    const float* lin2_b = (const float*)d_in[17];
    const float* g2 = (const float*)d_in[18];
    const float* be2 = (const float*)d_in[19];
    const float* lin3_w = (const float*)d_in[20];
    const float* lin3_b = (const float*)d_in[21];
    const float* g3 = (const float*)d_in[22];
    const float* be3 = (const float*)d_in[23];
    const float* lin4_w = (const float*)d_in[24];
    const float* lin4_b = (const float*)d_in[25];

    const int N = in_sizes[0] / INW;   // 50000
    const int E = in_sizes[1] / 2;     // 800000
    const int* src = ei;
    const int* dst = ei + E;

    float *zl, *zr, *agg, *h, *cnt, *inv, *pool, *pcnt, *cA, *cB;
    cudaGetSymbolAddress((void**)&zl, g_zl);
    cudaGetSymbolAddress((void**)&zr, g_zr);
    cudaGetSymbolAddress((void**)&agg, g_agg);
    cudaGetSymbolAddress((void**)&h, g_h);
    cudaGetSymbolAddress((void**)&cnt, g_cnt);
    cudaGetSymbolAddress((void**)&inv, g_inv);
    cudaGetSymbolAddress((void**)&pool, g_pool);
    cudaGetSymbolAddress((void**)&pcnt, g_pcnt);
    cudaGetSymbolAddress((void**)&cA, g_cA);
    cudaGetSymbolAddress((void**)&cB, g_cB);

    const int SMEM1 = (INW * 128 + 32 * INW) * 4;   // 81920
    const int SMEM2 = (64 * 128 + 32 * 64) * 4;     // 40960
    cudaFuncSetAttribute(k_gemm_dual<128>, cudaFuncAttributeMaxDynamicSharedMemorySize, SMEM1);
    cudaFuncSetAttribute(k_gemm_dual<64>, cudaFuncAttributeMaxDynamicSharedMemorySize, SMEM2);

    const int gemm_blocks = (N + 31) / 32;
    const long long sc_threads = (long long)E * 16;
    const int sc_blocks = (int)((sc_threads + 255) / 256);
    const long long cb_threads = (long long)N * 16;
    const int cb_blocks = (int)((cb_threads + 255) / 256);

    // degree counts (same for all layers)
    cudaMemsetAsync(cnt, 0, (size_t)N * sizeof(float), 0);
    k_count<<<(E + 255) / 256, 256>>>(dst, cnt, E);
    k_inv<<<(N + 255) / 256, 256>>>(cnt, inv, N);

    // ---- layer 1 ----
    k_gemm_dual<128><<<gemm_blocks, 256, SMEM1>>>(x, W1l, W1r, zl, zr, N);
    cudaMemsetAsync(agg, 0, (size_t)N * 64 * sizeof(float), 0);
    k_scatter<<<sc_blocks, 256>>>(src, dst, zl, agg, E);
    k_combine<<<cb_blocks, 256>>>(agg, inv, zr, b1l, h, N);

    // ---- layer 2 ----
    k_gemm_dual<64><<<gemm_blocks, 256, SMEM2>>>(h, W2l, W2r, zl, zr, N);
    cudaMemsetAsync(agg, 0, (size_t)N * 64 * sizeof(float), 0);
    k_scatter<<<sc_blocks, 256>>>(src, dst, zl, agg, E);
    k_combine<<<cb_blocks, 256>>>(agg, inv, zr, b2l, h, N);

    // ---- layer 3 ----
    k_gemm_dual<64><<<gemm_blocks, 256, SMEM2>>>(h, W3l, W3r, zl, zr, N);
    cudaMemsetAsync(agg, 0, (size_t)N * 64 * sizeof(float), 0);
    k_scatter<<<sc_blocks, 256>>>(src, dst, zl, agg, E);
    k_combine<<<cb_blocks, 256>>>(agg, inv, zr, b3l, h, N);

    // ---- global mean pool ----
    cudaMemsetAsync(pool, 0, (size_t)GG * 64 * sizeof(float), 0);
    cudaMemsetAsync(pcnt, 0, (size_t)GG * sizeof(float), 0);
    k_pool<<<cb_blocks, 256>>>(h, batch, pool, pcnt, N);
    k_poolfin<<<(GG * 64 + 255) / 256, 256>>>(pool, pcnt, cA);

    // ---- MLP head ----
    k_lin_bn_tanh<<<256, 256>>>(cA, 64, lin1_w, lin1_b, g1, be1, cB, 256);
    k_lin_bn_tanh<<<128, 256>>>(cB, 256, lin2_w, lin2_b, g2, be2, cA, 128);
    k_lin_bn_tanh<<<64, 256>>>(cA, 128, lin3_w, lin3_b, g3, be3, cB, 64);
    k_final<<<1, 256>>>(cB, lin4_w, lin4_b, (float*)d_out);
}

// round 7
// speedup vs baseline: 1.2735x; 1.2735x over previous
#include <cuda_runtime.h>
#include <cstdint>

// ---------------- problem constants ----------------
#define NN 50000
#define EE 800000
#define GG 256
#define HH 64
#define INW 128
#define SCAN_BLK 512
#define NBLK ((NN + SCAN_BLK - 1) / SCAN_BLK)   // 98

// ---------------- device scratch (no allocation allowed) ----------------
__device__ float g_zl[NN * HH];
__device__ float g_zr[NN * HH];
__device__ float g_h[NN * HH];
__device__ int   g_cnt[NN];
__device__ int   g_offs[NN + 1];
__device__ int   g_cursor[NN];
__device__ int   g_csr[EE];
__device__ int   g_bsum[128];
__device__ float g_pool[GG * HH];
__device__ float g_pcnt[GG];
__device__ float g_cA[GG * 256];
__device__ float g_cB[GG * 256];

// ---------------- helpers ----------------
__device__ __forceinline__ void red_add_v4(float* a, float4 v) {
    asm volatile("red.global.add.v4.f32 [%0], {%1,%2,%3,%4};"
                 :: "l"(a), "f"(v.x), "f"(v.y), "f"(v.z), "f"(v.w) : "memory");
}
__device__ __forceinline__ void red_add_f(float* a, float v) {
    asm volatile("red.global.add.f32 [%0], %1;" :: "l"(a), "f"(v) : "memory");
}

// ---------------- CSR build ----------------
__global__ void k_count(const int* __restrict__ dst, int* __restrict__ cnt, int E) {
    int e = blockIdx.x * blockDim.x + threadIdx.x;
    if (e >= E) return;
    unsigned d = (unsigned)dst[e];
    if (d < NN) atomicAdd(cnt + d, 1);
}

// block-wise exclusive scan (Hillis-Steele over SCAN_BLK)
__global__ void k_scan1(const int* __restrict__ cnt, int* __restrict__ offs,
                        int* __restrict__ bsum, int N) {
    __shared__ int sh[SCAN_BLK];
    int i = blockIdx.x * SCAN_BLK + threadIdx.x;
    int v = (i < N) ? cnt[i] : 0;
    sh[threadIdx.x] = v;
    __syncthreads();
    for (int d = 1; d < SCAN_BLK; d <<= 1) {
        int t = (threadIdx.x >= d) ? sh[threadIdx.x - d] : 0;
        __syncthreads();
        sh[threadIdx.x] += t;
        __syncthreads();
    }
    if (i < N) offs[i] = sh[threadIdx.x] - v;   // exclusive
    if (threadIdx.x == SCAN_BLK - 1) bsum[blockIdx.x] = sh[SCAN_BLK - 1];
}

__global__ void k_scan2(int* __restrict__ bsum, int nb) {
    __shared__ int sh[128];
    int v = (threadIdx.x < nb) ? bsum[threadIdx.x] : 0;
    sh[threadIdx.x] = v;
    __syncthreads();
    for (int d = 1; d < 128; d <<= 1) {
        int t = (threadIdx.x >= d) ? sh[threadIdx.x - d] : 0;
        __syncthreads();
        sh[threadIdx.x] += t;
        __syncthreads();
    }
    if (threadIdx.x < nb) bsum[threadIdx.x] = sh[threadIdx.x] - v;   // exclusive
}

__global__ void k_scan3(int* __restrict__ offs, const int* __restrict__ bsum,
                        int* __restrict__ cursor, int N, int E) {
    int i = blockIdx.x * blockDim.x + threadIdx.x;
    if (i < N) {
        int o = offs[i] + bsum[i / SCAN_BLK];
        offs[i] = o;
        cursor[i] = o;
    }
    if (i == 0) offs[N] = E;
}

__global__ void k_fill(const int* __restrict__ src, const int* __restrict__ dst,
                       int* __restrict__ cursor, int* __restrict__ csr, int E) {
    int e = blockIdx.x * blockDim.x + threadIdx.x;
    if (e >= E) return;
    unsigned s = (unsigned)src[e];
    unsigned d = (unsigned)dst[e];
    if (s >= NN || d >= NN) return;
    int pos = atomicAdd(cursor + d, 1);
    csr[pos] = (int)s;
}

// ---------------- dual GEMM: z = x @ [Wl | Wr]  (DIN x 64 each) ----------------
template <int DIN>
__global__ void k_gemm_dual(const float* __restrict__ x,
                            const float* __restrict__ Wl,
                            const float* __restrict__ Wr,
                            float* __restrict__ zl,
                            float* __restrict__ zr, int N) {
    extern __shared__ float sm[];
    float* ws = sm;                 // DIN * 128
    float* xs = sm + DIN * 128;     // 32 * DIN
    const int tid = threadIdx.x;

    for (int i = tid; i < DIN * 128; i += 256) {
        int k = i >> 7, j = i & 127;
        ws[i] = (j < 64) ? Wl[k * 64 + j] : Wr[k * 64 + (j - 64)];
    }
    const int base = blockIdx.x * 32;
    for (int i = tid; i < 32 * DIN; i += 256) {
        int n = i / DIN, k = i % DIN;
        int node = base + n;
        xs[i] = (node < N) ? x[(long long)node * DIN + k] : 0.0f;
    }
    __syncthreads();

    const int tx = tid & 31;
    const int ty = tid >> 5;
    float acc[4][4];
#pragma unroll
    for (int a = 0; a < 4; a++)
#pragma unroll
        for (int b = 0; b < 4; b++) acc[a][b] = 0.0f;

    const float* xs0 = xs + (ty * 4) * DIN;
#pragma unroll 4
    for (int k = 0; k < DIN; k++) {
        float4 w = *(const float4*)(ws + k * 128 + tx * 4);
        float xv[4];
#pragma unroll
        for (int a = 0; a < 4; a++) xv[a] = xs0[a * DIN + k];
#pragma unroll
        for (int a = 0; a < 4; a++) {
            acc[a][0] += xv[a] * w.x;
            acc[a][1] += xv[a] * w.y;
            acc[a][2] += xv[a] * w.z;
            acc[a][3] += xv[a] * w.w;
        }
    }

    const int col = tx * 4;
#pragma unroll
    for (int a = 0; a < 4; a++) {
        int node = base + ty * 4 + a;
        if (node < N) {
            float4 v = make_float4(acc[a][0], acc[a][1], acc[a][2], acc[a][3]);
            if (col < 64)
                *(float4*)(zl + (long long)node * 64 + col) = v;
            else
                *(float4*)(zr + (long long)node * 64 + (col - 64)) = v;
        }
    }
}

// ---------------- CSR gather + combine: h = mean_{src in N(dst)} zl[src] + zr + b ----------------
// 16 threads per node, each owns 4 cols (float4). Pure reads, no atomics.
__global__ void k_gather(const int* __restrict__ offs, const int* __restrict__ csr,
                         const float* __restrict__ zl, const float* __restrict__ zr,
                         const float* __restrict__ bl, float* __restrict__ h, int N) {
    int tid = threadIdx.x;
    int node = blockIdx.x * 16 + (tid >> 4);
    int c = (tid & 15) * 4;
    if (node >= N) return;
    int s0 = offs[node], s1 = offs[node + 1];
    float4 acc = make_float4(0.f, 0.f, 0.f, 0.f);
    int i = s0;
    int nxt = (i < s1) ? __ldg(csr + i) : 0;
    for (; i < s1;) {
        int s = nxt;
        ++i;
        nxt = (i < s1) ? __ldg(csr + i) : 0;
        float4 v = *(const float4*)(zl + (long long)s * 64 + c);
        acc.x += v.x; acc.y += v.y; acc.z += v.z; acc.w += v.w;
    }
    float iv = 1.0f / fmaxf((float)(s1 - s0), 1.0f);
    float4 r = *(const float4*)(zr + (long long)node * 64 + c);
    float4 b = *(const float4*)(bl + c);
    float4 o;
    o.x = acc.x * iv + r.x + b.x;
    o.y = acc.y * iv + r.y + b.y;
    o.z = acc.z * iv + r.z + b.z;
    o.w = acc.w * iv + r.w + b.w;
    *(float4*)(h + (long long)node * 64 + c) = o;
}

// layer-3 variant: fuse global mean-pool accumulation, skip writing h
__global__ void k_gather_pool(const int* __restrict__ offs, const int* __restrict__ csr,
                              const float* __restrict__ zl, const float* __restrict__ zr,
                              const float* __restrict__ bl, const int* __restrict__ batch,
                              float* __restrict__ pool, float* __restrict__ pcnt, int N) {
    int tid = threadIdx.x;
    int node = blockIdx.x * 16 + (tid >> 4);
    int c = (tid & 15) * 4;
    if (node >= N) return;
    int s0 = offs[node], s1 = offs[node + 1];
    float4 acc = make_float4(0.f, 0.f, 0.f, 0.f);
    int i = s0;
    int nxt = (i < s1) ? __ldg(csr + i) : 0;
    for (; i < s1;) {
        int s = nxt;
        ++i;
        nxt = (i < s1) ? __ldg(csr + i) : 0;
        float4 v = *(const float4*)(zl + (long long)s * 64 + c);
        acc.x += v.x; acc.y += v.y; acc.z += v.z; acc.w += v.w;
    }
    float iv = 1.0f / fmaxf((float)(s1 - s0), 1.0f);
    float4 r = *(const float4*)(zr + (long long)node * 64 + c);
    float4 b = *(const float4*)(bl + c);
    float4 o;
    o.x = acc.x * iv + r.x + b.x;
    o.y = acc.y * iv + r.y + b.y;
    o.z = acc.z * iv + r.z + b.z;
    o.w = acc.w * iv + r.w + b.w;
    unsigned g = (unsigned)batch[node];
    if (g < GG) {
        red_add_v4(pool + (long long)g * 64 + c, o);
        if (c == 0) red_add_f(pcnt + g, 1.0f);
    }
}

__global__ void k_poolfin(const float* __restrict__ pool, const float* __restrict__ pcnt,
                          float* __restrict__ c0) {
    int idx = blockIdx.x * blockDim.x + threadIdx.x;
    if (idx >= GG * 64) return;
    int g = idx >> 6;
    c0[idx] = pool[idx] / fmaxf(pcnt[g], 1.0f);
}

// ---------------- fused Linear + BatchNorm(batch stats) + tanh ----------------
__global__ void k_lin_bn_tanh(const float* __restrict__ in, int din,
                              const float* __restrict__ W, const float* __restrict__ b,
                              const float* __restrict__ gamma, const float* __restrict__ beta,
                              float* __restrict__ out, int dout) {
    __shared__ float ws[256];
    __shared__ float red[256];
    const int col = blockIdx.x;
    const int tid = threadIdx.x;
    if (tid < din) ws[tid] = W[tid * dout + col];
    __syncthreads();

    float val = b[col];
    const float* row = in + tid * din;
    for (int k = 0; k < din; k++) val += row[k] * ws[k];

    red[tid] = val;
    __syncthreads();
    for (int s = 128; s > 0; s >>= 1) {
        if (tid < s) red[tid] += red[tid + s];
        __syncthreads();
    }
    float mean = red[0] * (1.0f / 256.0f);
    __syncthreads();

    float dv = val - mean;
    red[tid] = dv * dv;
    __syncthreads();
    for (int s = 128; s > 0; s >>= 1) {
        if (tid < s) red[tid] += red[tid + s];
        __syncthreads();
    }
    float var = red[0] * (1.0f / 256.0f);

    float y = dv * rsqrtf(var + 1e-5f) * gamma[col] + beta[col];
    out[tid * dout + col] = tanhf(y);
}

// ---------------- final linear 64 -> 10 ----------------
__global__ void k_final(const float* __restrict__ in, const float* __restrict__ W,
                        const float* __restrict__ b, float* __restrict__ out) {
    __shared__ float ws[64 * 10];
    __shared__ float bs[10];
    const int tid = threadIdx.x;
    for (int i = tid; i < 640; i += 256) ws[i] = W[i];
    if (tid < 10) bs[tid] = b[tid];
    __syncthreads();
    float acc[10];
#pragma unroll
    for (int j = 0; j < 10; j++) acc[j] = bs[j];
    const float* row = in + tid * 64;
    for (int k = 0; k < 64; k++) {
        float xv = row[k];
#pragma unroll
        for (int j = 0; j < 10; j++) acc[j] += xv * ws[k * 10 + j];
    }
#pragma unroll
    for (int j = 0; j < 10; j++) out[tid * 10 + j] = acc[j];
}

// ---------------- launch ----------------
extern "C" void kernel_launch(void* const* d_in, const int* in_sizes, int n_in,
                              void* d_out, int out_size) {
    const float* x = (const float*)d_in[0];
    const int* ei = (const int*)d_in[1];
    const int* batch = (const int*)d_in[2];
    const float* W1l = (const float*)d_in[3];
    const float* b1l = (const float*)d_in[4];
    const float* W1r = (const float*)d_in[5];
    const float* W2l = (const float*)d_in[6];
    const float* b2l = (const float*)d_in[7];
    const float* W2r = (const float*)d_in[8];
    const float* W3l = (const float*)d_in[9];
    const float* b3l = (const float*)d_in[10];
    const float* W3r = (const float*)d_in[11];
    const float* lin1_w = (const float*)d_in[12];
    const float* lin1_b = (const float*)d_in[13];
    const float* g1 = (const float*)d_in[14];
    const float* be1 = (const float*)d_in[15];
    const float* lin2_w = (const float*)d_in[16];
    const float* lin2_b = (const float*)d_in[17];
    const float* g2 = (const float*)d_in[18];
    const float* be2 = (const float*)d_in[19];
    const float* lin3_w = (const float*)d_in[20];
    const float* lin3_b = (const float*)d_in[21];
    const float* g3 = (const float*)d_in[22];
    const float* be3 = (const float*)d_in[23];
    const float* lin4_w = (const float*)d_in[24];
    const float* lin4_b = (const float*)d_in[25];

    const int N = in_sizes[0] / INW;   // 50000
    const int E = in_sizes[1] / 2;     // 800000
    const int* src = ei;
    const int* dst = ei + E;

    float *zl, *zr, *h, *pool, *pcnt, *cA, *cB;
    int *cnt, *offs, *cursor, *csr, *bsum;
    cudaGetSymbolAddress((void**)&zl, g_zl);
    cudaGetSymbolAddress((void**)&zr, g_zr);
    cudaGetSymbolAddress((void**)&h, g_h);
    cudaGetSymbolAddress((void**)&cnt, g_cnt);
    cudaGetSymbolAddress((void**)&offs, g_offs);
    cudaGetSymbolAddress((void**)&cursor, g_cursor);
    cudaGetSymbolAddress((void**)&csr, g_csr);
    cudaGetSymbolAddress((void**)&bsum, g_bsum);
    cudaGetSymbolAddress((void**)&pool, g_pool);
    cudaGetSymbolAddress((void**)&pcnt, g_pcnt);
    cudaGetSymbolAddress((void**)&cA, g_cA);
    cudaGetSymbolAddress((void**)&cB, g_cB);

    const int SMEM1 = (INW * 128 + 32 * INW) * 4;   // 81920
    const int SMEM2 = (64 * 128 + 32 * 64) * 4;     // 40960
    cudaFuncSetAttribute(k_gemm_dual<128>, cudaFuncAttributeMaxDynamicSharedMemorySize, SMEM1);
    cudaFuncSetAttribute(k_gemm_dual<64>, cudaFuncAttributeMaxDynamicSharedMemorySize, SMEM2);

    const int gemm_blocks = (N + 31) / 32;
    const int gat_blocks = (N + 15) / 16;

    // ---- CSR build (once, reused by all 3 layers) ----
    cudaMemsetAsync(cnt, 0, (size_t)N * sizeof(int), 0);
    k_count<<<(E + 255) / 256, 256>>>(dst, cnt, E);
    k_scan1<<<NBLK, SCAN_BLK>>>(cnt, offs, bsum, N);
    k_scan2<<<1, 128>>>(bsum, NBLK);
    k_scan3<<<(N + 255) / 256, 256>>>(offs, bsum, cursor, N, E);
    k_fill<<<(E + 255) / 256, 256>>>(src, dst, cursor, csr, E);

    // ---- layer 1 ----
    k_gemm_dual<128><<<gemm_blocks, 256, SMEM1>>>(x, W1l, W1r, zl, zr, N);
    k_gather<<<gat_blocks, 256>>>(offs, csr, zl, zr, b1l, h, N);

    // ---- layer 2 ----
    k_gemm_dual<64><<<gemm_blocks, 256, SMEM2>>>(h, W2l, W2r, zl, zr, N);
    k_gather<<<gat_blocks, 256>>>(offs, csr, zl, zr, b2l, h, N);

    // ---- layer 3 + fused global mean pool ----
    k_gemm_dual<64><<<gemm_blocks, 256, SMEM2>>>(h, W3l, W3r, zl, zr, N);
    cudaMemsetAsync(pool, 0, (size_t)GG * 64 * sizeof(float), 0);
    cudaMemsetAsync(pcnt, 0, (size_t)GG * sizeof(float), 0);
    k_gather_pool<<<gat_blocks, 256>>>(offs, csr, zl, zr, b3l, batch, pool, pcnt, N);
    k_poolfin<<<(GG * 64 + 255) / 256, 256>>>(pool, pcnt, cA);

    // ---- MLP head ----
    k_lin_bn_tanh<<<256, 256>>>(cA, 64, lin1_w, lin1_b, g1, be1, cB, 256);
    k_lin_bn_tanh<<<128, 256>>>(cB, 256, lin2_w, lin2_b, g2, be2, cA, 128);
    k_lin_bn_tanh<<<64, 256>>>(cA, 128, lin3_w, lin3_b, g3, be3, cB, 64);
    k_final<<<1, 256>>>(cB, lin4_w, lin4_b, (float*)d_out);
}